// round 3
// baseline (speedup 1.0000x reference)
#include <cuda_runtime.h>

#define T_      16384
#define CHUNK   64
#define WARM    192        // 96 cheap + 96 full (self-start chunks only)
#define NCH     (T_ / CHUNK)

// Full step: all three series, emit outputs.
#define STEP(xv, m, g, h) do {                   \
    es  = fmaf(b_s, es, a_s * (xv));             \
    el  = fmaf(b_l, el, a_l * (xv));             \
    (m) = es - el;                               \
    sig = fmaf(b_g, sig, a_g * (m));             \
    (g) = sig;                                   \
    (h) = (m) - sig;                             \
} while (0)

// Warmup step with signal chain.
#define STEPW(xv) do {                           \
    es  = fmaf(b_s, es, a_s * (xv));             \
    el  = fmaf(b_l, el, a_l * (xv));             \
    float _m = es - el;                          \
    sig = fmaf(b_g, sig, a_g * _m);              \
} while (0)

// Cheap warmup step: input EMAs only.
#define STEPA(xv) do {                           \
    es  = fmaf(b_s, es, a_s * (xv));             \
    el  = fmaf(b_l, el, a_l * (xv));             \
} while (0)

__global__ __launch_bounds__(256)
void macd_chunked_kernel(const float* __restrict__ x,
                         const int*   __restrict__ p_short,
                         const int*   __restrict__ p_long,
                         const int*   __restrict__ p_sig,
                         float* __restrict__ out_macd,
                         float* __restrict__ out_sig,
                         float* __restrict__ out_hist,
                         int B)
{
    const int tid = blockIdx.x * blockDim.x + threadIdx.x;
    const int row = tid / NCH;
    const int ch  = tid - row * NCH;
    if (row >= B) return;

    const float a_s = 2.0f / (float)(p_short[0] + 1);
    const float a_l = 2.0f / (float)(p_long[0]  + 1);
    const float a_g = 2.0f / (float)(p_sig[0]   + 1);
    const float b_s = 1.0f - a_s;
    const float b_l = 1.0f - a_l;
    const float b_g = 1.0f - a_g;

    const float* xr    = x + (size_t)row * T_;
    const int    start = ch * CHUNK;

    float es, el, sig;

    if (ch != 0) {
        if (start < WARM) {
            // Warmup window would underflow the row: run EXACTLY from t=0.
            // Reference init: es=el=x[0]; sig_0 = macd_0 = 0 (exact, since
            // macd_0 = x0 - x0 = 0 and signal EMA inits to macd_0).
            const float4* pw = (const float4*)xr;
            float4 v = pw[0];
            es = v.x; el = v.x; sig = 0.0f;
            STEPW(v.y); STEPW(v.z); STEPW(v.w);
            const int n4 = start / 4;
            #pragma unroll 4
            for (int i = 1; i < n4; ++i) {
                float4 u = pw[i];
                STEPW(u.x); STEPW(u.y); STEPW(u.z); STEPW(u.w);
            }
        } else {
            // Self-start warmup over [start-WARM, start).
            const float4* pw = (const float4*)(xr + (start - WARM));
            // Phase 1: 96 elements, input EMAs only.
            float4 v = pw[0];
            es = v.x; el = v.x;
            STEPA(v.y); STEPA(v.z); STEPA(v.w);
            #pragma unroll 4
            for (int i = 1; i < 24; ++i) {
                float4 u = pw[i];
                STEPA(u.x); STEPA(u.y); STEPA(u.z); STEPA(u.w);
            }
            // Phase 2: 96 elements, full state (signal self-starts at 0).
            sig = 0.0f;
            #pragma unroll 4
            for (int i = 24; i < 48; ++i) {
                float4 u = pw[i];
                STEPW(u.x); STEPW(u.y); STEPW(u.z); STEPW(u.w);
            }
        }
    }

    const size_t base = (size_t)row * T_ + start;
    float* __restrict__ om = out_macd + base;
    float* __restrict__ og = out_sig  + base;
    float* __restrict__ oh = out_hist + base;
    const float4* __restrict__ px = (const float4*)(xr + start);

    int i0 = 0;
    if (ch == 0) {
        // Exact reference init.
        float4 v = px[0];
        es = v.x; el = v.x; sig = 0.0f;
        float m1, m2, m3, g1, g2, g3, h1, h2, h3;
        STEP(v.y, m1, g1, h1);
        STEP(v.z, m2, g2, h2);
        STEP(v.w, m3, g3, h3);
        ((float4*)om)[0] = make_float4(0.0f, m1, m2, m3);
        ((float4*)og)[0] = make_float4(0.0f, g1, g2, g3);
        ((float4*)oh)[0] = make_float4(0.0f, h1, h2, h3);
        i0 = 1;
    }

    #pragma unroll 4
    for (int i = i0; i < CHUNK / 4; ++i) {
        float4 v = px[i];
        float m0, m1, m2, m3, g0, g1, g2, g3, h0, h1, h2, h3;
        STEP(v.x, m0, g0, h0);
        STEP(v.y, m1, g1, h1);
        STEP(v.z, m2, g2, h2);
        STEP(v.w, m3, g3, h3);
        ((float4*)om)[i] = make_float4(m0, m1, m2, m3);
        ((float4*)og)[i] = make_float4(g0, g1, g2, g3);
        ((float4*)oh)[i] = make_float4(h0, h1, h2, h3);
    }
}

extern "C" void kernel_launch(void* const* d_in, const int* in_sizes, int n_in,
                              void* d_out, int out_size)
{
    const float* x       = (const float*)d_in[0];
    const int*   p_short = (const int*)d_in[1];
    const int*   p_long  = (const int*)d_in[2];
    const int*   p_sig   = (const int*)d_in[3];

    const int B = in_sizes[0] / T_;
    float* out = (float*)d_out;
    const size_t N = (size_t)B * T_;

    const int total   = B * NCH;
    const int threads = 256;
    const int blocks  = (total + threads - 1) / threads;

    macd_chunked_kernel<<<blocks, threads>>>(
        x, p_short, p_long, p_sig,
        out, out + N, out + 2 * N, B);
}

// round 4
// speedup vs baseline: 2.2005x; 2.2005x over previous
#include <cuda_runtime.h>

#define T_      16384
#define CHUNK   128
#define WARM    160
#define TILE    32
#define WTILES  (WARM / TILE)        // 5
#define MTILES  (CHUNK / TILE)       // 4
#define SPAN    (32 * CHUNK)         // 4096 elements per warp
#define SPANS   (T_ / SPAN)          // 4 spans per row
#define WPC     4                    // warps per CTA
#define PAD     33                   // smem row stride (conflict-free)

// Full step: updates es/el/sig, emits macd (m) and signal (g).
#define STEP(xv, m, g) do {                      \
    es  = fmaf(b_s, es, a_s * (xv));             \
    el  = fmaf(b_l, el, a_l * (xv));             \
    (m) = es - el;                               \
    sig = fmaf(b_g, sig, a_g * (m));             \
    (g) = sig;                                   \
} while (0)

// Warmup step: state only.
#define STEPW(xv) do {                           \
    es  = fmaf(b_s, es, a_s * (xv));             \
    el  = fmaf(b_l, el, a_l * (xv));             \
    float _m = es - el;                          \
    sig = fmaf(b_g, sig, a_g * _m);              \
} while (0)

__global__ __launch_bounds__(32 * WPC)
void macd_tiled(const float* __restrict__ x,
                const int*   __restrict__ p_s,
                const int*   __restrict__ p_l,
                const int*   __restrict__ p_g,
                float* __restrict__ out, int B)
{
    // Per-warp staging: tin doubles as input tile AND macd stage (in-place);
    // tg holds the signal stage. [lane][elem] layout, stride PAD=33.
    __shared__ float sm_in[WPC][32 * PAD];
    __shared__ float sm_g [WPC][32 * PAD];

    const int lane = threadIdx.x & 31;
    const int wib  = threadIdx.x >> 5;
    const int w    = blockIdx.x * WPC + wib;
    const int row  = w / SPANS;
    const int span = w - row * SPANS;
    if (row >= B) return;

    const float a_s = 2.0f / (float)(p_s[0] + 1);
    const float a_l = 2.0f / (float)(p_l[0] + 1);
    const float a_g = 2.0f / (float)(p_g[0] + 1);
    const float b_s = 1.0f - a_s;
    const float b_l = 1.0f - a_l;
    const float b_g = 1.0f - a_g;

    const float* __restrict__ xr = x + (size_t)row * T_;
    const size_t N        = (size_t)B * T_;
    const int    span_off = span * SPAN;
    const int    cstart   = span_off + lane * CHUNK;   // this lane's chunk start

    float* __restrict__ tin = sm_in[wib];
    float* __restrict__ tg  = sm_g[wib];

    const int sh = lane >> 3;     // segment-high within gather (0..3)
    const int f4 = (lane & 7) * 4;

    // Init state at the (clamped) warmup start. Running a STEP on x[ws] with
    // es=el=x[ws], sig=0 is an exact no-op, so no element is special-cased.
    int ws = cstart - WARM; if (ws < 0) ws = 0;
    float es = __ldg(xr + ws);
    float el = es;
    float sig = 0.0f;

    // ---------------- warmup: 5 tiles of 32 ----------------
    #pragma unroll 1
    for (int t = 0; t < WTILES; ++t) {
        // Coalesced gather: warp-LDG covers 4 full 128B lines.
        #pragma unroll
        for (int k = 0; k < 8; ++k) {
            const int s   = 4 * k + sh;                       // chunk (= smem row)
            int idx = span_off + s * CHUNK - WARM + t * TILE + f4;
            if (idx < 0) idx = 0;                             // clamp (values unused)
            const float4 v = *(const float4*)(xr + idx);
            const int o = s * PAD + f4;
            tin[o] = v.x; tin[o+1] = v.y; tin[o+2] = v.z; tin[o+3] = v.w;
        }
        __syncwarp();
        // Tile active iff its window start is inside the row (row-start spans:
        // inactive tiles are skipped; active ones give exact history from t=0).
        if (cstart - WARM + t * TILE >= 0) {
            const float* mine = tin + lane * PAD;
            #pragma unroll
            for (int i = 0; i < TILE; ++i) { const float xv = mine[i]; STEPW(xv); }
        }
        __syncwarp();
    }

    // ---------------- main: 4 tiles of 32 ----------------
    float* __restrict__ om = out;
    float* __restrict__ og = out + N;
    float* __restrict__ oh = out + 2 * N;

    #pragma unroll 1
    for (int t = 0; t < MTILES; ++t) {
        #pragma unroll
        for (int k = 0; k < 8; ++k) {
            const int s   = 4 * k + sh;
            const int idx = span_off + s * CHUNK + t * TILE + f4;
            const float4 v = *(const float4*)(xr + idx);
            const int o = s * PAD + f4;
            tin[o] = v.x; tin[o+1] = v.y; tin[o+2] = v.z; tin[o+3] = v.w;
        }
        __syncwarp();
        {
            float* __restrict__ mine = tin + lane * PAD;
            float* __restrict__ gm   = tg  + lane * PAD;
            #pragma unroll
            for (int b = 0; b < 4; ++b) {
                float xv[8];
                #pragma unroll
                for (int j = 0; j < 8; ++j) xv[j] = mine[b * 8 + j];
                #pragma unroll
                for (int j = 0; j < 8; ++j) {
                    float m, g;
                    STEP(xv[j], m, g);
                    mine[b * 8 + j] = m;   // macd staged in place
                    gm[b * 8 + j]   = g;   // signal staged
                }
            }
        }
        __syncwarp();
        // Coalesced stores: per warp-STG, 4 full 128B lines. hist = m - g.
        #pragma unroll
        for (int k = 0; k < 8; ++k) {
            const int s = 4 * k + sh;
            const int o = s * PAD + f4;
            const float m0 = tin[o], m1 = tin[o+1], m2 = tin[o+2], m3 = tin[o+3];
            const float g0 = tg[o],  g1 = tg[o+1],  g2 = tg[o+2],  g3 = tg[o+3];
            const size_t go = (size_t)row * T_ + span_off + s * CHUNK + t * TILE + f4;
            *(float4*)(om + go) = make_float4(m0, m1, m2, m3);
            *(float4*)(og + go) = make_float4(g0, g1, g2, g3);
            *(float4*)(oh + go) = make_float4(m0 - g0, m1 - g1, m2 - g2, m3 - g3);
        }
        __syncwarp();
    }
}

extern "C" void kernel_launch(void* const* d_in, const int* in_sizes, int n_in,
                              void* d_out, int out_size)
{
    const float* x   = (const float*)d_in[0];
    const int*   ps  = (const int*)d_in[1];
    const int*   pl  = (const int*)d_in[2];
    const int*   pg  = (const int*)d_in[3];

    const int B = in_sizes[0] / T_;
    float* out = (float*)d_out;

    const int total_warps = B * SPANS;
    const int blocks = (total_warps + WPC - 1) / WPC;

    macd_tiled<<<blocks, 32 * WPC>>>(x, ps, pl, pg, out, B);
}

// round 5
// speedup vs baseline: 2.3896x; 1.0859x over previous
#include <cuda_runtime.h>

#define T_    16384
#define TILE  256              // elements per warp-tile (8 per lane)
#define SPAN  2048             // output elements per warp
#define SPANS (T_ / SPAN)      // 8 warps per row
#define MT    (SPAN / TILE)    // 8 main tiles per warp
#define WPC   4
#define FULL  0xffffffffu

struct Ser { float b, w1, w2, w3, w4, w5, pw; };

__device__ __forceinline__ Ser make_ser(float b, int lane) {
    Ser s; s.b = b;
    float b2 = b * b, b4 = b2 * b2;
    s.w1 = b4 * b4;          // b^8
    s.w2 = s.w1 * s.w1;      // b^16
    s.w3 = s.w2 * s.w2;      // b^32
    s.w4 = s.w3 * s.w3;      // b^64
    s.w5 = s.w4 * s.w4;      // b^128
    // pw = b^(8*lane), exact square-and-multiply on lane bits
    float pw = 1.f, p = s.w1;
#pragma unroll
    for (int k = 0; k < 5; ++k) { if (lane & (1 << k)) pw *= p; p *= p; }
    s.pw = pw;
    return s;
}

// Inclusive affine scan of one EMA series over a 256-elt tile.
// ax[i] = a * x_i for this lane's 8 elements. On exit y[i] = EMA value,
// S updated to the state after the tile's last element.
__device__ __forceinline__ void scan8(const Ser s, const float ax[8],
                                      float y[8], float& S, int lane)
{
    // Local segment value (zero-history): B = sum_i ax[i] * b^(7-i)
    float Bv = ax[0];
#pragma unroll
    for (int i = 1; i < 8; ++i) Bv = fmaf(s.b, Bv, ax[i]);
    // Kogge-Stone across lanes; incoming block weight is b^(8*2^k).
    float t;
    t = __shfl_up_sync(FULL, Bv, 1);  if (lane >= 1)  Bv = fmaf(s.w1, t, Bv);
    t = __shfl_up_sync(FULL, Bv, 2);  if (lane >= 2)  Bv = fmaf(s.w2, t, Bv);
    t = __shfl_up_sync(FULL, Bv, 4);  if (lane >= 4)  Bv = fmaf(s.w3, t, Bv);
    t = __shfl_up_sync(FULL, Bv, 8);  if (lane >= 8)  Bv = fmaf(s.w4, t, Bv);
    t = __shfl_up_sync(FULL, Bv, 16); if (lane >= 16) Bv = fmaf(s.w5, t, Bv);
    // State entering this lane = zero-history prefix of earlier lanes + carried S.
    float sb = __shfl_up_sync(FULL, Bv, 1);
    sb = (lane == 0) ? 0.f : sb;
    float e = fmaf(s.pw, S, sb);
    // Reconstruct the lane's 8 values.
#pragma unroll
    for (int i = 0; i < 8; ++i) { e = fmaf(s.b, e, ax[i]); y[i] = e; }
    S = __shfl_sync(FULL, e, 31);
}

__global__ __launch_bounds__(32 * WPC)
void macd_scan(const float* __restrict__ x,
               const int* __restrict__ ps_, const int* __restrict__ pl_,
               const int* __restrict__ pg_,
               float* __restrict__ out, int B)
{
    const int lane = threadIdx.x & 31;
    const int w    = blockIdx.x * WPC + (threadIdx.x >> 5);
    const int row  = w / SPANS;
    const int span = w - row * SPANS;
    if (row >= B) return;

    const float a_s = 2.f / (float)(ps_[0] + 1), b_s = 1.f - a_s;
    const float a_l = 2.f / (float)(pl_[0] + 1), b_l = 1.f - a_l;
    const float a_g = 2.f / (float)(pg_[0] + 1), b_g = 1.f - a_g;
    const Ser ss = make_ser(b_s, lane);
    const Ser sl = make_ser(b_l, lane);
    const Ser sg = make_ser(b_g, lane);

    const size_t rbase = (size_t)row * T_;
    const int    off0  = span * SPAN;
    const size_t N     = (size_t)B * T_;
    float* __restrict__ om = out;
    float* __restrict__ og = out + N;
    float* __restrict__ oh = out + 2 * N;

    // Carries. Init S = x[first] makes the first EMA step an exact identity
    // (b*x + a*x = x), matching the reference init y_0 = x_0; sig starts 0.
    float Ss, Sl, Sg = 0.f;

    if (span == 0) {
        const float x0 = __ldg(x + rbase);
        Ss = x0; Sl = x0;
    } else {
        // One warmup tile over [off0-256, off0): self-start, decays to <3e-9.
        const size_t base = rbase + (size_t)(off0 - TILE) + lane * 8;
        const float x0 = __ldg(x + rbase + (off0 - TILE));
        Ss = x0; Sl = x0;
        const float4 v0 = *(const float4*)(x + base);
        const float4 v1 = *(const float4*)(x + base + 4);
        const float xv[8] = {v0.x, v0.y, v0.z, v0.w, v1.x, v1.y, v1.z, v1.w};
        float axs[8], axl[8], ys[8], yl[8];
#pragma unroll
        for (int i = 0; i < 8; ++i) { axs[i] = a_s * xv[i]; axl[i] = a_l * xv[i]; }
        scan8(ss, axs, ys, Ss, lane);
        scan8(sl, axl, yl, Sl, lane);
        float axg[8], yg[8];
#pragma unroll
        for (int i = 0; i < 8; ++i) axg[i] = a_g * (ys[i] - yl[i]);
        scan8(sg, axg, yg, Sg, lane);
    }

#pragma unroll 2
    for (int t = 0; t < MT; ++t) {
        const size_t base = rbase + (size_t)off0 + t * TILE + lane * 8;
        const float4 v0 = *(const float4*)(x + base);
        const float4 v1 = *(const float4*)(x + base + 4);
        const float xv[8] = {v0.x, v0.y, v0.z, v0.w, v1.x, v1.y, v1.z, v1.w};
        float axs[8], axl[8], ys[8], yl[8];
#pragma unroll
        for (int i = 0; i < 8; ++i) { axs[i] = a_s * xv[i]; axl[i] = a_l * xv[i]; }
        scan8(ss, axs, ys, Ss, lane);
        scan8(sl, axl, yl, Sl, lane);
        float m[8], axg[8], yg[8];
#pragma unroll
        for (int i = 0; i < 8; ++i) { m[i] = ys[i] - yl[i]; axg[i] = a_g * m[i]; }
        scan8(sg, axg, yg, Sg, lane);

        *(float4*)(om + base)     = make_float4(m[0], m[1], m[2], m[3]);
        *(float4*)(om + base + 4) = make_float4(m[4], m[5], m[6], m[7]);
        *(float4*)(og + base)     = make_float4(yg[0], yg[1], yg[2], yg[3]);
        *(float4*)(og + base + 4) = make_float4(yg[4], yg[5], yg[6], yg[7]);
        *(float4*)(oh + base)     = make_float4(m[0] - yg[0], m[1] - yg[1],
                                                m[2] - yg[2], m[3] - yg[3]);
        *(float4*)(oh + base + 4) = make_float4(m[4] - yg[4], m[5] - yg[5],
                                                m[6] - yg[6], m[7] - yg[7]);
    }
}

extern "C" void kernel_launch(void* const* d_in, const int* in_sizes, int n_in,
                              void* d_out, int out_size)
{
    const float* x  = (const float*)d_in[0];
    const int*   ps = (const int*)d_in[1];
    const int*   pl = (const int*)d_in[2];
    const int*   pg = (const int*)d_in[3];

    const int B = in_sizes[0] / T_;
    float* out = (float*)d_out;

    const int total_warps = B * SPANS;
    const int blocks = (total_warps + WPC - 1) / WPC;

    macd_scan<<<blocks, 32 * WPC>>>(x, ps, pl, pg, out, B);
}